// round 1
// baseline (speedup 1.0000x reference)
#include <cuda_runtime.h>
#include <cuda_bf16.h>

#define B_BATCH 16
#define NSEG 9          // K_MAX+1 segments, 0 = background
#define EPSF 1e-5f
#define SIGMA_AGG 0.5f
#define SIGMA_DIS 3.0f

// per-batch scratch: [0..8]=ck, [9..17]=ct, [18..26]=A, [27..35]=Bsame, [36..44]=D,
// [45..47]=region dice (inter, pp, gg), [48..50]=kernel dice
__device__ float g_scratch[B_BATCH * 64];

__global__ void zero_scratch() {
    int i = blockIdx.x * blockDim.x + threadIdx.x;
    if (i < B_BATCH * 64) g_scratch[i] = 0.f;
}

__global__ __launch_bounds__(256) void stats_kernel(
    const float* __restrict__ pr, const float* __restrict__ rg,
    const float* __restrict__ pk, const float* __restrict__ kg,
    const float* __restrict__ sim, const int* __restrict__ tlab,
    const int* __restrict__ klab, int npix)
{
    const int b = blockIdx.y;
    __shared__ float s_seg[45];
    __shared__ float s_dice[6];
    for (int i = threadIdx.x; i < 45; i += blockDim.x) s_seg[i] = 0.f;
    if (threadIdx.x < 6) s_dice[threadIdx.x] = 0.f;
    __syncthreads();

    const size_t base = (size_t)b * npix;
    const float4* __restrict__ pr4 = (const float4*)(pr + base);
    const float4* __restrict__ rg4 = (const float4*)(rg + base);
    const float4* __restrict__ pk4 = (const float4*)(pk + base);
    const float4* __restrict__ kg4 = (const float4*)(kg + base);
    const size_t sbase = (size_t)b * 4 * npix;
    const float4* __restrict__ c0p = (const float4*)(sim + sbase);
    const float4* __restrict__ c1p = (const float4*)(sim + sbase + npix);
    const float4* __restrict__ c2p = (const float4*)(sim + sbase + 2 * (size_t)npix);
    const float4* __restrict__ c3p = (const float4*)(sim + sbase + 3 * (size_t)npix);
    const int4* __restrict__ tl4 = (const int4*)(tlab + base);
    const int4* __restrict__ kl4 = (const int4*)(klab + base);

    float d0 = 0.f, d1 = 0.f, d2 = 0.f, d3 = 0.f, d4 = 0.f, d5 = 0.f;
    const int nvec = npix >> 2;
    const int lane = threadIdx.x & 31;
    const int stride = gridDim.x * blockDim.x;

    for (int v = blockIdx.x * blockDim.x + threadIdx.x; v < nvec; v += stride) {
        float4 a  = pr4[v];
        float4 g  = rg4[v];
        float4 pb = pk4[v];
        float4 gb = kg4[v];
        float4 c0 = c0p[v];
        float4 c1 = c1p[v];
        float4 c2 = c2p[v];
        float4 c3 = c3p[v];
        int4 tl = tl4[v];
        int4 kl = kl4[v];

#define DO_COMP(comp)                                                           \
        {                                                                       \
            float sg = 1.f / (1.f + __expf(-a.comp));                           \
            float gv = g.comp;                                                  \
            d0 += sg * gv; d1 += sg * sg; d2 += gv * gv;                        \
            sg = 1.f / (1.f + __expf(-pb.comp));                                \
            gv = gb.comp;                                                       \
            d3 += sg * gv; d4 += sg * sg; d5 += gv * gv;                        \
            float s2 = c0.comp * c0.comp + c1.comp * c1.comp                    \
                     + c2.comp * c2.comp + c3.comp * c3.comp;                   \
            int t = tl.comp, k = kl.comp;                                       \
            unsigned mt = __match_any_sync(0xffffffffu, t);                     \
            if ((__ffs(mt) - 1) == lane)                                        \
                atomicAdd(&s_seg[9 + t], (float)__popc(mt));                    \
            unsigned mk = __match_any_sync(0xffffffffu, k);                     \
            if ((__ffs(mk) - 1) == lane)                                        \
                atomicAdd(&s_seg[k], (float)__popc(mk));                        \
            if (t == k) {                                                       \
                atomicAdd(&s_seg[27 + t], s2);                                  \
            } else {                                                            \
                atomicAdd(&s_seg[18 + t], s2);                                  \
                atomicAdd(&s_seg[36 + k], s2);                                  \
            }                                                                   \
        }
        DO_COMP(x) DO_COMP(y) DO_COMP(z) DO_COMP(w)
#undef DO_COMP
    }

    // warp-reduce dice partials, one shared atomic per warp per stat
#pragma unroll
    for (int off = 16; off; off >>= 1) {
        d0 += __shfl_down_sync(0xffffffffu, d0, off);
        d1 += __shfl_down_sync(0xffffffffu, d1, off);
        d2 += __shfl_down_sync(0xffffffffu, d2, off);
        d3 += __shfl_down_sync(0xffffffffu, d3, off);
        d4 += __shfl_down_sync(0xffffffffu, d4, off);
        d5 += __shfl_down_sync(0xffffffffu, d5, off);
    }
    if (lane == 0) {
        atomicAdd(&s_dice[0], d0);
        atomicAdd(&s_dice[1], d1);
        atomicAdd(&s_dice[2], d2);
        atomicAdd(&s_dice[3], d3);
        atomicAdd(&s_dice[4], d4);
        atomicAdd(&s_dice[5], d5);
    }
    __syncthreads();

    if (threadIdx.x < 45)
        atomicAdd(&g_scratch[b * 64 + threadIdx.x], s_seg[threadIdx.x]);
    else if (threadIdx.x < 51)
        atomicAdd(&g_scratch[b * 64 + threadIdx.x], s_dice[threadIdx.x - 45]);
}

__global__ void finalize_kernel(float* __restrict__ out)
{
    const int lane = threadIdx.x;
    float lr = 0.f, lk = 0.f, lagg = 0.f, ldis = 0.f;
    if (lane < B_BATCH) {
        const float* s = &g_scratch[lane * 64];
        float ck[NSEG], ct[NSEG], Av[NSEG], Bv[NSEG], Dv[NSEG];
#pragma unroll
        for (int i = 0; i < NSEG; i++) {
            ck[i] = s[i];
            ct[i] = s[9 + i];
            Av[i] = s[18 + i];
            Bv[i] = s[27 + i];
            Dv[i] = s[36 + i];
        }
        // dice losses (per-sample, summed across batch via shuffle below)
        float inter = s[45], pp = s[46], gg = s[47];
        lr = 1.f - (2.f * inter + EPSF) / ((pp + EPSF) + (gg + EPSF));
        inter = s[48]; pp = s[49]; gg = s[50];
        lk = 1.f - (2.f * inter + EPSF) / ((pp + EPSF) + (gg + EPSF));

        float av[NSEG - 1];
#pragma unroll
        for (int i = 1; i < NSEG; i++) {
            float inv = 1.f / (ck[i] + 1.f);
            float omi = 1.f - inv;
            float n2 = Av[i] + Bv[i] * omi * omi + Dv[i] * inv * inv;
            float nrm = sqrtf(n2);
            float t = nrm - SIGMA_AGG;                 // no clamp (matches ref)
            lagg += logf(t * t + 1.f) / (ct[i] + 1.f);
            float den = ck[i] + 0.001f;
            av[i - 1] = (Bv[i] + Dv[i]) / (den * den);
        }
#pragma unroll
        for (int i = 0; i < NSEG - 1; i++) {
#pragma unroll
            for (int j = i + 1; j < NSEG - 1; j++) {
                float p = SIGMA_DIS - sqrtf(av[i] + av[j]);
                ldis += logf(p * p + 1.f);
            }
        }
        ldis *= (1.f / 56.f);   // K_MAX * (K_MAX - 1) = 56
    }
#pragma unroll
    for (int off = 16; off; off >>= 1) {
        lr   += __shfl_down_sync(0xffffffffu, lr,   off);
        lk   += __shfl_down_sync(0xffffffffu, lk,   off);
        lagg += __shfl_down_sync(0xffffffffu, lagg, off);
        ldis += __shfl_down_sync(0xffffffffu, ldis, off);
    }
    if (lane == 0) {
        out[0] = lr + 0.5f * lk + 0.25f * (lagg + ldis);
        out[1] = lr;
        out[2] = lk;
        out[3] = lagg;
        out[4] = ldis;
    }
}

extern "C" void kernel_launch(void* const* d_in, const int* in_sizes, int n_in,
                              void* d_out, int out_size)
{
    const float* pr  = (const float*)d_in[0];   // pred_regions
    const float* rg  = (const float*)d_in[1];   // regions_gt
    const float* pk  = (const float*)d_in[2];   // pred_kernels
    const float* kg  = (const float*)d_in[3];   // kernels_gt
    const float* sim = (const float*)d_in[4];   // pred_similarities (B,4,H,W)
    const int*   tl  = (const int*)d_in[5];     // text labels
    const int*   kl  = (const int*)d_in[6];     // kernel labels
    const int npix = in_sizes[0] / B_BATCH;     // H*W = 409600

    zero_scratch<<<2, 512>>>();
    dim3 grid(74, B_BATCH);                     // 1184 blocks = one 8-block/SM wave
    stats_kernel<<<grid, 256>>>(pr, rg, pk, kg, sim, tl, kl, npix);
    finalize_kernel<<<1, 32>>>((float*)d_out);
}

// round 3
// speedup vs baseline: 1.3977x; 1.3977x over previous
#include <cuda_runtime.h>
#include <cuda_bf16.h>

#define B_BATCH 16
#define GX 37               // blocks per batch -> 37*16 = 592 CTAs = 4/SM on 148 SMs
#define THREADS 256
#define NSEG 9
#define EPSF 1e-5f
#define SIGMA_AGG 0.5f
#define SIGMA_DIS 3.0f

// Per-(block.x, batch) partial record, 64 floats each:
// [0..8]=A (t, t!=k), [9..17]=B (t==k), [18..26]=D (k, t!=k),
// [27..35]=packed counts (u32: ct low16, ck high16),
// [36..41]=dice partials (r_inter, r_pp, r_gg, k_inter, k_pp, k_gg)
__device__ float g_part[GX * B_BATCH * 64];

__global__ __launch_bounds__(THREADS) void stats_kernel(
    const float* __restrict__ pr, const float* __restrict__ rg,
    const float* __restrict__ pk, const float* __restrict__ kg,
    const float* __restrict__ sim, const int* __restrict__ tlab,
    const int* __restrict__ klab, int npix)
{
    // Bin-major layout: bins[bin][THREADS]. Bank = tid&31 -> conflict-free.
    __shared__ float    s_f[27 * THREADS];   // A(0-8), B(9-17), D(18-26)
    __shared__ unsigned s_c[9 * THREADS];    // packed ct/ck
    __shared__ float    s_dice[6];

    const int tid = threadIdx.x;
    const int b = blockIdx.y;

    for (int i = tid; i < 27 * THREADS; i += THREADS) s_f[i] = 0.f;
    for (int i = tid; i < 9 * THREADS; i += THREADS) s_c[i] = 0u;
    if (tid < 6) s_dice[tid] = 0.f;
    __syncthreads();

    const size_t base = (size_t)b * npix;
    const float4* __restrict__ pr4 = (const float4*)(pr + base);
    const float4* __restrict__ rg4 = (const float4*)(rg + base);
    const float4* __restrict__ pk4 = (const float4*)(pk + base);
    const float4* __restrict__ kg4 = (const float4*)(kg + base);
    const size_t sbase = (size_t)b * 4 * npix;
    const float4* __restrict__ c0p = (const float4*)(sim + sbase);
    const float4* __restrict__ c1p = (const float4*)(sim + sbase + npix);
    const float4* __restrict__ c2p = (const float4*)(sim + sbase + 2 * (size_t)npix);
    const float4* __restrict__ c3p = (const float4*)(sim + sbase + 3 * (size_t)npix);
    const int4* __restrict__ tl4 = (const int4*)(tlab + base);
    const int4* __restrict__ kl4 = (const int4*)(klab + base);

    float d0 = 0.f, d1 = 0.f, d2 = 0.f, d3 = 0.f, d4 = 0.f, d5 = 0.f;
    const int nvec = npix >> 2;
    const int stride = GX * THREADS;

    for (int v = blockIdx.x * THREADS + tid; v < nvec; v += stride) {
        float4 a  = pr4[v];
        float4 g  = rg4[v];
        float4 pb = pk4[v];
        float4 gb = kg4[v];
        float4 c0 = c0p[v];
        float4 c1 = c1p[v];
        float4 c2 = c2p[v];
        float4 c3 = c3p[v];
        int4 tl = tl4[v];
        int4 kl = kl4[v];

#define DO_COMP(comp)                                                          \
        {                                                                      \
            float sg = 1.f / (1.f + __expf(-a.comp));                          \
            float gv = g.comp;                                                 \
            d0 += sg * gv; d1 += sg * sg; d2 += gv * gv;                       \
            sg = 1.f / (1.f + __expf(-pb.comp));                               \
            gv = gb.comp;                                                      \
            d3 += sg * gv; d4 += sg * sg; d5 += gv * gv;                       \
            float s2 = c0.comp * c0.comp + c1.comp * c1.comp                   \
                     + c2.comp * c2.comp + c3.comp * c3.comp;                  \
            int t = tl.comp, k = kl.comp;                                      \
            if (t == k) {                                                      \
                s_c[(t << 8) + tid] += 0x10001u;                               \
                s_f[((9 + t) << 8) + tid] += s2;                               \
            } else {                                                           \
                s_c[(t << 8) + tid] += 1u;                                     \
                s_c[(k << 8) + tid] += 0x10000u;                               \
                s_f[(t << 8) + tid] += s2;                                     \
                s_f[((18 + k) << 8) + tid] += s2;                              \
            }                                                                  \
        }
        DO_COMP(x) DO_COMP(y) DO_COMP(z) DO_COMP(w)
#undef DO_COMP
    }

    // dice: warp shuffle reduce, one shared atomic per warp per stat (48 lanes total)
    const int lane = tid & 31;
#pragma unroll
    for (int off = 16; off; off >>= 1) {
        d0 += __shfl_down_sync(0xffffffffu, d0, off);
        d1 += __shfl_down_sync(0xffffffffu, d1, off);
        d2 += __shfl_down_sync(0xffffffffu, d2, off);
        d3 += __shfl_down_sync(0xffffffffu, d3, off);
        d4 += __shfl_down_sync(0xffffffffu, d4, off);
        d5 += __shfl_down_sync(0xffffffffu, d5, off);
    }
    if (lane == 0) {
        atomicAdd(&s_dice[0], d0);
        atomicAdd(&s_dice[1], d1);
        atomicAdd(&s_dice[2], d2);
        atomicAdd(&s_dice[3], d3);
        atomicAdd(&s_dice[4], d4);
        atomicAdd(&s_dice[5], d5);
    }
    __syncthreads();

    // Block reduction: 8 warps fan out over bins; write one partial record.
    const int wid = tid >> 5;
    const int rec = (blockIdx.x * B_BATCH + b) * 64;

    for (int bin = wid; bin < 27; bin += 8) {
        float vsum = 0.f;
#pragma unroll
        for (int j = 0; j < 8; j++) vsum += s_f[(bin << 8) + lane + (j << 5)];
#pragma unroll
        for (int off = 16; off; off >>= 1)
            vsum += __shfl_down_sync(0xffffffffu, vsum, off);
        if (lane == 0) g_part[rec + bin] = vsum;
    }
    for (int bin = wid; bin < 9; bin += 8) {
        unsigned csum = 0u;
#pragma unroll
        for (int j = 0; j < 8; j++) csum += s_c[(bin << 8) + lane + (j << 5)];
#pragma unroll
        for (int off = 16; off; off >>= 1)
            csum += __shfl_down_sync(0xffffffffu, csum, off);
        if (lane == 0) g_part[rec + 27 + bin] = __uint_as_float(csum);
    }
    if (tid < 6) g_part[rec + 36 + tid] = s_dice[tid];
}

// One block, 832 threads: 816 (=16*51) reduction tasks + per-batch math in warp 0.
// s_stats layout per batch: [0..8]=A, [9..17]=B, [18..26]=D, [27..35]=ct,
// [36..44]=ck, [45..50]=dice
__global__ __launch_bounds__(832) void finalize_kernel(float* __restrict__ out)
{
    __shared__ float s_stats[B_BATCH][52];
    const int tid = threadIdx.x;

    if (tid < B_BATCH * 51) {
        const int b = tid / 51;
        const int s = tid % 51;
        float acc = 0.f;
        if (s < 27) {                       // A/B/D float sums
#pragma unroll 4
            for (int bx = 0; bx < GX; bx++)
                acc += g_part[(bx * B_BATCH + b) * 64 + s];
        } else if (s < 36) {                // ct: low 16 bits of packed slot
            unsigned u = 0;
#pragma unroll 4
            for (int bx = 0; bx < GX; bx++)
                u += __float_as_uint(g_part[(bx * B_BATCH + b) * 64 + 27 + (s - 27)]) & 0xffffu;
            acc = (float)u;
        } else if (s < 45) {                // ck: high 16 bits
            unsigned u = 0;
#pragma unroll 4
            for (int bx = 0; bx < GX; bx++)
                u += __float_as_uint(g_part[(bx * B_BATCH + b) * 64 + 27 + (s - 36)]) >> 16;
            acc = (float)u;
        } else {                            // dice
#pragma unroll 4
            for (int bx = 0; bx < GX; bx++)
                acc += g_part[(bx * B_BATCH + b) * 64 + 36 + (s - 45)];
        }
        s_stats[b][s] = acc;
    }
    __syncthreads();

    if (tid < 32) {
        float lr = 0.f, lk = 0.f, lagg = 0.f, ldis = 0.f;
        if (tid < B_BATCH) {
            const float* s = s_stats[tid];
            float inter = s[45], pp = s[46], gg = s[47];
            lr = 1.f - (2.f * inter + EPSF) / ((pp + EPSF) + (gg + EPSF));
            inter = s[48]; pp = s[49]; gg = s[50];
            lk = 1.f - (2.f * inter + EPSF) / ((pp + EPSF) + (gg + EPSF));

            float av[NSEG - 1];
#pragma unroll
            for (int i = 1; i < NSEG; i++) {
                float ck = s[36 + i], ct = s[27 + i];
                float A = s[i], Bv = s[9 + i], D = s[18 + i];
                float inv = 1.f / (ck + 1.f);
                float omi = 1.f - inv;
                float n2 = A + Bv * omi * omi + D * inv * inv;
                float tt = sqrtf(n2) - SIGMA_AGG;       // no clamp (matches ref)
                lagg += logf(tt * tt + 1.f) / (ct + 1.f);
                float den = ck + 0.001f;
                av[i - 1] = (Bv + D) / (den * den);
            }
#pragma unroll
            for (int i = 0; i < NSEG - 1; i++)
#pragma unroll
                for (int j = i + 1; j < NSEG - 1; j++) {
                    float p = SIGMA_DIS - sqrtf(av[i] + av[j]);
                    ldis += logf(p * p + 1.f);
                }
            ldis *= (1.f / 56.f);                       // K_MAX*(K_MAX-1)
        }
#pragma unroll
        for (int off = 16; off; off >>= 1) {
            lr   += __shfl_down_sync(0xffffffffu, lr,   off);
            lk   += __shfl_down_sync(0xffffffffu, lk,   off);
            lagg += __shfl_down_sync(0xffffffffu, lagg, off);
            ldis += __shfl_down_sync(0xffffffffu, ldis, off);
        }
        if (tid == 0) {
            out[0] = lr + 0.5f * lk + 0.25f * (lagg + ldis);
            out[1] = lr;
            out[2] = lk;
            out[3] = lagg;
            out[4] = ldis;
        }
    }
}

extern "C" void kernel_launch(void* const* d_in, const int* in_sizes, int n_in,
                              void* d_out, int out_size)
{
    const float* pr  = (const float*)d_in[0];   // pred_regions
    const float* rg  = (const float*)d_in[1];   // regions_gt
    const float* pk  = (const float*)d_in[2];   // pred_kernels
    const float* kg  = (const float*)d_in[3];   // kernels_gt
    const float* sim = (const float*)d_in[4];   // pred_similarities (B,4,H,W)
    const int*   tl  = (const int*)d_in[5];     // text labels
    const int*   kl  = (const int*)d_in[6];     // kernel labels
    const int npix = in_sizes[0] / B_BATCH;     // H*W = 409600

    dim3 grid(GX, B_BATCH);                     // 592 CTAs = 4/SM
    stats_kernel<<<grid, THREADS>>>(pr, rg, pk, kg, sim, tl, kl, npix);
    finalize_kernel<<<1, 832>>>((float*)d_out);
}

// round 5
// speedup vs baseline: 1.7269x; 1.2355x over previous
#include <cuda_runtime.h>
#include <cuda_bf16.h>

#define B_BATCH 16
#define GX 37               // 37*16 = 592 CTAs = exactly 4/SM on 148 SMs
#define THREADS 256
#define NSEG 9
#define NBLOCKS (GX * B_BATCH)
#define EPSF 1e-5f
#define SIGMA_AGG 0.5f
#define SIGMA_DIS 3.0f

// Global accumulators (.bss zero-init at module load; last block re-zeros
// after each call so every graph replay starts clean).
// g_statsF per batch: [0..8]=A (t, t!=k), [9..17]=B (t==k), [18..26]=D (k, t!=k),
//                     [27..32]=dice (r_inter, r_pp, r_gg, k_inter, k_pp, k_gg)
__device__ float    g_statsF[B_BATCH][33];
__device__ unsigned g_cnt[B_BATCH][18];     // [0..8]=ct, [9..17]=ck
__device__ unsigned g_count;

__global__ __launch_bounds__(THREADS) void panloss_kernel(
    const float* __restrict__ pr, const float* __restrict__ rg,
    const float* __restrict__ pk, const float* __restrict__ kg,
    const float* __restrict__ sim, const int* __restrict__ tlab,
    const int* __restrict__ klab, int npix, float* __restrict__ out)
{
    // Private per-thread bins, bin-major: bank = tid&31 -> conflict-free.
    __shared__ float    s_f[27 * THREADS];   // A(0-8), B(9-17), D(18-26)
    __shared__ unsigned s_c[9 * THREADS];    // packed: ct low16, ck high16
    __shared__ float    s_dice[6];
    __shared__ unsigned s_last;

    const int tid = threadIdx.x;
    const int b = blockIdx.y;

    for (int i = tid; i < 27 * THREADS; i += THREADS) s_f[i] = 0.f;
    for (int i = tid; i < 9 * THREADS; i += THREADS) s_c[i] = 0u;
    if (tid < 6) s_dice[tid] = 0.f;
    __syncthreads();

    const size_t base = (size_t)b * npix;
    const float4* __restrict__ pr4 = (const float4*)(pr + base);
    const float4* __restrict__ rg4 = (const float4*)(rg + base);
    const float4* __restrict__ pk4 = (const float4*)(pk + base);
    const float4* __restrict__ kg4 = (const float4*)(kg + base);
    const size_t sbase = (size_t)b * 4 * npix;
    const float4* __restrict__ c0p = (const float4*)(sim + sbase);
    const float4* __restrict__ c1p = (const float4*)(sim + sbase + npix);
    const float4* __restrict__ c2p = (const float4*)(sim + sbase + 2 * (size_t)npix);
    const float4* __restrict__ c3p = (const float4*)(sim + sbase + 3 * (size_t)npix);
    const int4* __restrict__ tl4 = (const int4*)(tlab + base);
    const int4* __restrict__ kl4 = (const int4*)(klab + base);

    float d0 = 0.f, d1 = 0.f, d2 = 0.f, d3 = 0.f, d4 = 0.f, d5 = 0.f;
    const int nvec = npix >> 2;
    const int stride = GX * THREADS;

    for (int v = blockIdx.x * THREADS + tid; v < nvec; v += stride) {
        float4 a  = pr4[v];
        float4 g  = rg4[v];
        float4 pb = pk4[v];
        float4 gb = kg4[v];
        float4 c0 = c0p[v];
        float4 c1 = c1p[v];
        float4 c2 = c2p[v];
        float4 c3 = c3p[v];
        int4 tl = tl4[v];
        int4 kl = kl4[v];

#define DO_COMP(comp)                                                          \
        {                                                                      \
            float sg = 1.f / (1.f + __expf(-a.comp));                          \
            float gv = g.comp;                                                 \
            d0 += sg * gv; d1 += sg * sg; d2 += gv * gv;                       \
            sg = 1.f / (1.f + __expf(-pb.comp));                               \
            gv = gb.comp;                                                      \
            d3 += sg * gv; d4 += sg * sg; d5 += gv * gv;                       \
            float s2 = c0.comp * c0.comp + c1.comp * c1.comp                   \
                     + c2.comp * c2.comp + c3.comp * c3.comp;                  \
            int t = tl.comp, k = kl.comp;                                      \
            bool eq = (t == k);                                                \
            s_c[(t << 8) + tid] += eq ? 0x10001u : 1u;                         \
            s_c[(k << 8) + tid] += eq ? 0u : 0x10000u;                         \
            int bin1 = eq ? (9 + t) : t;                                       \
            s_f[(bin1 << 8) + tid] += s2;                                      \
            s_f[((18 + k) << 8) + tid] += eq ? 0.f : s2;                       \
        }
        DO_COMP(x) DO_COMP(y) DO_COMP(z) DO_COMP(w)
#undef DO_COMP
    }

    // dice: warp shuffle reduce, one shared atomic per warp per stat
    const int lane = tid & 31;
#pragma unroll
    for (int off = 16; off; off >>= 1) {
        d0 += __shfl_down_sync(0xffffffffu, d0, off);
        d1 += __shfl_down_sync(0xffffffffu, d1, off);
        d2 += __shfl_down_sync(0xffffffffu, d2, off);
        d3 += __shfl_down_sync(0xffffffffu, d3, off);
        d4 += __shfl_down_sync(0xffffffffu, d4, off);
        d5 += __shfl_down_sync(0xffffffffu, d5, off);
    }
    if (lane == 0) {
        atomicAdd(&s_dice[0], d0);
        atomicAdd(&s_dice[1], d1);
        atomicAdd(&s_dice[2], d2);
        atomicAdd(&s_dice[3], d3);
        atomicAdd(&s_dice[4], d4);
        atomicAdd(&s_dice[5], d5);
    }
    __syncthreads();

    // Block reduction: 8 warps fan out over bins; lane0 -> global atomicAdd.
    const int wid = tid >> 5;
    for (int bin = wid; bin < 27; bin += 8) {
        float vsum = 0.f;
#pragma unroll
        for (int j = 0; j < 8; j++) vsum += s_f[(bin << 8) + lane + (j << 5)];
#pragma unroll
        for (int off = 16; off; off >>= 1)
            vsum += __shfl_down_sync(0xffffffffu, vsum, off);
        if (lane == 0) atomicAdd(&g_statsF[b][bin], vsum);
    }
    for (int bin = wid; bin < 9; bin += 8) {
        unsigned csum = 0u;
#pragma unroll
        for (int j = 0; j < 8; j++) csum += s_c[(bin << 8) + lane + (j << 5)];
#pragma unroll
        for (int off = 16; off; off >>= 1)
            csum += __shfl_down_sync(0xffffffffu, csum, off);
        if (lane == 0) {
            atomicAdd(&g_cnt[b][bin], csum & 0xffffu);          // ct
            atomicAdd(&g_cnt[b][9 + bin], csum >> 16);          // ck
        }
    }
    if (tid < 6) atomicAdd(&g_statsF[b][27 + tid], s_dice[tid]);

    // Last-block-done pattern: fence, bump counter, last block finalizes.
    __threadfence();
    if (tid == 0)
        s_last = (atomicAdd(&g_count, 1u) == (unsigned)(NBLOCKS - 1));
    __syncthreads();
    if (!s_last) return;
    __threadfence();

    if (tid < 32) {
        float lr = 0.f, lk = 0.f, lagg = 0.f, ldis = 0.f;
        if (tid < B_BATCH) {
            const float* s = g_statsF[tid];
            const unsigned* c = g_cnt[tid];
            float inter = s[27], pp = s[28], gg = s[29];
            lr = 1.f - (2.f * inter + EPSF) / ((pp + EPSF) + (gg + EPSF));
            inter = s[30]; pp = s[31]; gg = s[32];
            lk = 1.f - (2.f * inter + EPSF) / ((pp + EPSF) + (gg + EPSF));

            float av[NSEG - 1];
#pragma unroll
            for (int i = 1; i < NSEG; i++) {
                float ct = (float)c[i];
                float ck = (float)c[9 + i];
                float A = s[i], Bv = s[9 + i], D = s[18 + i];
                float inv = 1.f / (ck + 1.f);
                float omi = 1.f - inv;
                float n2 = A + Bv * omi * omi + D * inv * inv;
                float tt = sqrtf(n2) - SIGMA_AGG;       // no clamp (matches ref)
                lagg += logf(tt * tt + 1.f) / (ct + 1.f);
                float den = ck + 0.001f;
                av[i - 1] = (Bv + D) / (den * den);
            }
#pragma unroll
            for (int i = 0; i < NSEG - 1; i++)
#pragma unroll
                for (int j = i + 1; j < NSEG - 1; j++) {
                    float p = SIGMA_DIS - sqrtf(av[i] + av[j]);
                    ldis += logf(p * p + 1.f);
                }
            ldis *= (1.f / 56.f);                       // K_MAX*(K_MAX-1)
        }
#pragma unroll
        for (int off = 16; off; off >>= 1) {
            lr   += __shfl_down_sync(0xffffffffu, lr,   off);
            lk   += __shfl_down_sync(0xffffffffu, lk,   off);
            lagg += __shfl_down_sync(0xffffffffu, lagg, off);
            ldis += __shfl_down_sync(0xffffffffu, ldis, off);
        }
        if (tid == 0) {
            out[0] = lr + 0.5f * lk + 0.25f * (lagg + ldis);
            out[1] = lr;
            out[2] = lk;
            out[3] = lagg;
            out[4] = ldis;
        }
    }
    __syncthreads();
    // Re-zero accumulators for the next call / graph replay.
    for (int i = tid; i < B_BATCH * 33; i += THREADS) ((float*)g_statsF)[i] = 0.f;
    for (int i = tid; i < B_BATCH * 18; i += THREADS) ((unsigned*)g_cnt)[i] = 0u;
    if (tid == 0) g_count = 0u;
}

extern "C" void kernel_launch(void* const* d_in, const int* in_sizes, int n_in,
                              void* d_out, int out_size)
{
    const float* pr  = (const float*)d_in[0];   // pred_regions
    const float* rg  = (const float*)d_in[1];   // regions_gt
    const float* pk  = (const float*)d_in[2];   // pred_kernels
    const float* kg  = (const float*)d_in[3];   // kernels_gt
    const float* sim = (const float*)d_in[4];   // pred_similarities (B,4,H,W)
    const int*   tl  = (const int*)d_in[5];     // text labels
    const int*   kl  = (const int*)d_in[6];     // kernel labels
    const int npix = in_sizes[0] / B_BATCH;     // H*W = 409600

    dim3 grid(GX, B_BATCH);                     // 592 CTAs = 4/SM
    panloss_kernel<<<grid, THREADS>>>(pr, rg, pk, kg, sim, tl, kl, npix,
                                      (float*)d_out);
}

// round 9
// speedup vs baseline: 2.0113x; 1.1647x over previous
#include <cuda_runtime.h>
#include <cuda_bf16.h>

#define B_BATCH 16
#define GX 37               // 37*16 = 592 CTAs = exactly 4/SM on 148 SMs
#define THREADS 256
#define NSEG 9
#define NBLOCKS (GX * B_BATCH)
#define EPSF 1e-5f
#define SIGMA_AGG 0.5f
#define SIGMA_DIS 3.0f

// Global accumulators (.bss zero-init at module load; last block re-zeros
// after each call so every graph replay starts clean).
// g_statsF per batch: [0..8]=A (t, t!=k), [9..17]=B (t==k), [18..26]=D (k, t!=k),
//                     [27..32]=dice (r_inter, r_pp, r_gg, k_inter, k_pp, k_gg)
__device__ float    g_statsF[B_BATCH][33];
__device__ unsigned g_cnt[B_BATCH][18];     // [0..8]=ct, [9..17]=ck
__device__ unsigned g_count;

__global__ __launch_bounds__(THREADS, 4) void panloss_kernel(
    const float* __restrict__ pr, const float* __restrict__ rg,
    const float* __restrict__ pk, const float* __restrict__ kg,
    const float* __restrict__ sim, const int* __restrict__ tlab,
    const int* __restrict__ klab, int npix, float* __restrict__ out)
{
    // Private per-thread bins, bin-major: bank = tid&31 -> conflict-free.
    __shared__ float    s_f[27 * THREADS];   // A(0-8), B(9-17), D(18-26)
    __shared__ unsigned s_c[9 * THREADS];    // packed: ct low16, ck high16
    __shared__ float    s_dice[6];
    __shared__ unsigned s_last;

    const int tid = threadIdx.x;
    const int b = blockIdx.y;

    for (int i = tid; i < 27 * THREADS; i += THREADS) s_f[i] = 0.f;
    for (int i = tid; i < 9 * THREADS; i += THREADS) s_c[i] = 0u;
    if (tid < 6) s_dice[tid] = 0.f;
    __syncthreads();

    const size_t base = (size_t)b * npix;
    const float4* __restrict__ pr4 = (const float4*)(pr + base);
    const float4* __restrict__ rg4 = (const float4*)(rg + base);
    const float4* __restrict__ pk4 = (const float4*)(pk + base);
    const float4* __restrict__ kg4 = (const float4*)(kg + base);
    const size_t sbase = (size_t)b * 4 * npix;
    const float4* __restrict__ c0p = (const float4*)(sim + sbase);
    const float4* __restrict__ c1p = (const float4*)(sim + sbase + npix);
    const float4* __restrict__ c2p = (const float4*)(sim + sbase + 2 * (size_t)npix);
    const float4* __restrict__ c3p = (const float4*)(sim + sbase + 3 * (size_t)npix);
    const int4* __restrict__ tl4 = (const int4*)(tlab + base);
    const int4* __restrict__ kl4 = (const int4*)(klab + base);

    float d0 = 0.f, d1 = 0.f, d2 = 0.f, d3 = 0.f, d4 = 0.f, d5 = 0.f;
    const int nvec = npix >> 2;
    const int stride = GX * THREADS;

    for (int v = blockIdx.x * THREADS + tid; v < nvec; v += stride) {
        float4 a  = pr4[v];
        float4 g  = rg4[v];
        float4 pb = pk4[v];
        float4 gb = kg4[v];
        float4 c0 = c0p[v];
        float4 c1 = c1p[v];
        float4 c2 = c2p[v];
        float4 c3 = c3p[v];
        int4 tl = tl4[v];
        int4 kl = kl4[v];

#define DO_COMP(comp)                                                          \
        {                                                                      \
            float sg = 1.f / (1.f + __expf(-a.comp));                          \
            float gv = g.comp;                                                 \
            d0 += sg * gv; d1 += sg * sg; d2 += gv * gv;                       \
            sg = 1.f / (1.f + __expf(-pb.comp));                               \
            gv = gb.comp;                                                      \
            d3 += sg * gv; d4 += sg * sg; d5 += gv * gv;                       \
            float s2 = c0.comp * c0.comp + c1.comp * c1.comp                   \
                     + c2.comp * c2.comp + c3.comp * c3.comp;                  \
            int t = tl.comp, k = kl.comp;                                      \
            bool eq = (t == k);                                                \
            s_c[(t << 8) + tid] += eq ? 0x10001u : 1u;                         \
            s_c[(k << 8) + tid] += eq ? 0u : 0x10000u;                         \
            int bin1 = eq ? (9 + t) : t;                                       \
            s_f[(bin1 << 8) + tid] += s2;                                      \
            s_f[((18 + k) << 8) + tid] += eq ? 0.f : s2;                       \
        }
        DO_COMP(x) DO_COMP(y) DO_COMP(z) DO_COMP(w)
#undef DO_COMP
    }

    // dice: warp shuffle reduce, one shared atomic per warp per stat
    const int lane = tid & 31;
#pragma unroll
    for (int off = 16; off; off >>= 1) {
        d0 += __shfl_down_sync(0xffffffffu, d0, off);
        d1 += __shfl_down_sync(0xffffffffu, d1, off);
        d2 += __shfl_down_sync(0xffffffffu, d2, off);
        d3 += __shfl_down_sync(0xffffffffu, d3, off);
        d4 += __shfl_down_sync(0xffffffffu, d4, off);
        d5 += __shfl_down_sync(0xffffffffu, d5, off);
    }
    if (lane == 0) {
        atomicAdd(&s_dice[0], d0);
        atomicAdd(&s_dice[1], d1);
        atomicAdd(&s_dice[2], d2);
        atomicAdd(&s_dice[3], d3);
        atomicAdd(&s_dice[4], d4);
        atomicAdd(&s_dice[5], d5);
    }
    __syncthreads();

    // Block reduction: 8 warps fan out over bins; lane0 -> global atomicAdd.
    const int wid = tid >> 5;
    for (int bin = wid; bin < 27; bin += 8) {
        float vsum = 0.f;
#pragma unroll
        for (int j = 0; j < 8; j++) vsum += s_f[(bin << 8) + lane + (j << 5)];
#pragma unroll
        for (int off = 16; off; off >>= 1)
            vsum += __shfl_down_sync(0xffffffffu, vsum, off);
        if (lane == 0) atomicAdd(&g_statsF[b][bin], vsum);
    }
    for (int bin = wid; bin < 9; bin += 8) {
        unsigned csum = 0u;
#pragma unroll
        for (int j = 0; j < 8; j++) csum += s_c[(bin << 8) + lane + (j << 5)];
#pragma unroll
        for (int off = 16; off; off >>= 1)
            csum += __shfl_down_sync(0xffffffffu, csum, off);
        if (lane == 0) {
            atomicAdd(&g_cnt[b][bin], csum & 0xffffu);          // ct
            atomicAdd(&g_cnt[b][9 + bin], csum >> 16);          // ck
        }
    }
    if (tid < 6) atomicAdd(&g_statsF[b][27 + tid], s_dice[tid]);

    // Last-block-done pattern: fence, bump counter, last block finalizes.
    __threadfence();
    if (tid == 0)
        s_last = (atomicAdd(&g_count, 1u) == (unsigned)(NBLOCKS - 1));
    __syncthreads();
    if (!s_last) return;
    __threadfence();

    if (tid < 32) {
        float lr = 0.f, lk = 0.f, lagg = 0.f, ldis = 0.f;
        if (tid < B_BATCH) {
            const float* s = g_statsF[tid];
            const unsigned* c = g_cnt[tid];
            float inter = s[27], pp = s[28], gg = s[29];
            lr = 1.f - (2.f * inter + EPSF) / ((pp + EPSF) + (gg + EPSF));
            inter = s[30]; pp = s[31]; gg = s[32];
            lk = 1.f - (2.f * inter + EPSF) / ((pp + EPSF) + (gg + EPSF));

            float av[NSEG - 1];
#pragma unroll
            for (int i = 1; i < NSEG; i++) {
                float ct = (float)c[i];
                float ck = (float)c[9 + i];
                float A = s[i], Bv = s[9 + i], D = s[18 + i];
                float inv = 1.f / (ck + 1.f);
                float omi = 1.f - inv;
                float n2 = A + Bv * omi * omi + D * inv * inv;
                float tt = sqrtf(n2) - SIGMA_AGG;       // no clamp (matches ref)
                lagg += logf(tt * tt + 1.f) / (ct + 1.f);
                float den = ck + 0.001f;
                av[i - 1] = (Bv + D) / (den * den);
            }
#pragma unroll
            for (int i = 0; i < NSEG - 1; i++)
#pragma unroll
                for (int j = i + 1; j < NSEG - 1; j++) {
                    float p = SIGMA_DIS - sqrtf(av[i] + av[j]);
                    ldis += logf(p * p + 1.f);
                }
            ldis *= (1.f / 56.f);                       // K_MAX*(K_MAX-1)
        }
#pragma unroll
        for (int off = 16; off; off >>= 1) {
            lr   += __shfl_down_sync(0xffffffffu, lr,   off);
            lk   += __shfl_down_sync(0xffffffffu, lk,   off);
            lagg += __shfl_down_sync(0xffffffffu, lagg, off);
            ldis += __shfl_down_sync(0xffffffffu, ldis, off);
        }
        if (tid == 0) {
            out[0] = lr + 0.5f * lk + 0.25f * (lagg + ldis);
            out[1] = lr;
            out[2] = lk;
            out[3] = lagg;
            out[4] = ldis;
        }
    }
    __syncthreads();
    // Re-zero accumulators for the next call / graph replay.
    for (int i = tid; i < B_BATCH * 33; i += THREADS) ((float*)g_statsF)[i] = 0.f;
    for (int i = tid; i < B_BATCH * 18; i += THREADS) ((unsigned*)g_cnt)[i] = 0u;
    if (tid == 0) g_count = 0u;
}

extern "C" void kernel_launch(void* const* d_in, const int* in_sizes, int n_in,
                              void* d_out, int out_size)
{
    const float* pr  = (const float*)d_in[0];   // pred_regions
    const float* rg  = (const float*)d_in[1];   // regions_gt
    const float* pk  = (const float*)d_in[2];   // pred_kernels
    const float* kg  = (const float*)d_in[3];   // kernels_gt
    const float* sim = (const float*)d_in[4];   // pred_similarities (B,4,H,W)
    const int*   tl  = (const int*)d_in[5];     // text labels
    const int*   kl  = (const int*)d_in[6];     // kernel labels
    const int npix = in_sizes[0] / B_BATCH;     // H*W = 409600

    dim3 grid(GX, B_BATCH);                     // 592 CTAs = 4/SM, single wave
    panloss_kernel<<<grid, THREADS>>>(pr, rg, pk, kg, sim, tl, kl, npix,
                                      (float*)d_out);
}